// round 7
// baseline (speedup 1.0000x reference)
#include <cuda_runtime.h>
#include <cstddef>

// ---------------------------------------------------------------------------
// Problem constants
// ---------------------------------------------------------------------------
#define D_      256      // STATE_DIM
#define ALEN_   128      // ACT_LEN
#define BSZ_    32       // batch
#define T_      2048     // sequence length
#define INDIM_  512      // padded input row
#define MROWS_  (BSZ_*T_)   // 65536 flattened (b,t) rows
#define CCH_    64       // scan chunks
#define LCH_    32       // chunk length  (CCH_*LCH_ == T_)

// ---------------------------------------------------------------------------
// Scratch (static device globals; no allocation allowed)
// ---------------------------------------------------------------------------
__device__ float g_c[(size_t)MROWS_ * D_];        // c[t] = Bu[t] + A_b + B_b   (64 MB)
__device__ float g_w[(size_t)MROWS_ * D_];        // inv_leaky(z1)              (64 MB)
__device__ float g_z0[BSZ_ * D_];                 // encoder output at t=0
__device__ float g_gbuf0[CCH_ * BSZ_ * D_];       // chunk-carry ping
__device__ float g_gbuf1[CCH_ * BSZ_ * D_];       // chunk-carry pong
__device__ float g_pows[11][D_ * D_];             // A^(2^i), i=1..10

__device__ __forceinline__ float leakyf(float x)    { return x < 0.f ? 0.01f * x : x; }
__device__ __forceinline__ float invleakyf(float x) { return x < 0.f ? x / 0.01f : x; }

// ---------------------------------------------------------------------------
// Generic fp32 GEMM:  out[m][n] = epi( sum_k X[m][k]*W'[n][k] + biases + add )
//   TRANSB=true : W'[n][k] = W[n*ldw + k]  (weights stored [out,in], the usual case)
//   TRANSB=false: W'[n][k] = W[k*ldw + n]  (plain X*W, used for matrix squaring)
// Tile: 64x64, BK=16, 256 threads, 4x4 register blocking.
// Assumes N % 64 == 0 and K % 16 == 0 (true for all call sites). M is guarded.
// ---------------------------------------------------------------------------
template<bool TRANSB, int EPI>   // EPI: 0 = none, 1 = inv_leaky
__global__ __launch_bounds__(256)
void gemm_k(const float* __restrict__ X, int ldx,
            const float* __restrict__ W, int ldw,
            const float* __restrict__ bias1,
            const float* __restrict__ bias2,
            const float* __restrict__ addsrc,   // optional, row stride N
            float* __restrict__ out,            // row stride N
            int M, int N, int K)
{
    __shared__ __align__(16) float As[16][64];
    __shared__ __align__(16) float Bs[16][64];
    const int tid = threadIdx.x;
    const int tx = tid & 15, ty = tid >> 4;
    const int m0 = blockIdx.y << 6, n0 = blockIdx.x << 6;
    const int lar = tid >> 2;          // 0..63
    const int lak = (tid & 3) << 2;    // 0,4,8,12

    float acc[4][4];
#pragma unroll
    for (int i = 0; i < 4; ++i)
#pragma unroll
        for (int j = 0; j < 4; ++j) acc[i][j] = 0.f;

    for (int k0 = 0; k0 < K; k0 += 16) {
        // --- A tile (input rows), guarded on M ---
        {
            float4 v = make_float4(0.f, 0.f, 0.f, 0.f);
            const int gm = m0 + lar;
            if (gm < M) v = *(const float4*)(X + (size_t)gm * ldx + k0 + lak);
            As[lak + 0][lar] = v.x; As[lak + 1][lar] = v.y;
            As[lak + 2][lar] = v.z; As[lak + 3][lar] = v.w;
        }
        // --- B tile ---
        if (TRANSB) {
            float4 v = *(const float4*)(W + (size_t)(n0 + lar) * ldw + k0 + lak);
            Bs[lak + 0][lar] = v.x; Bs[lak + 1][lar] = v.y;
            Bs[lak + 2][lar] = v.z; Bs[lak + 3][lar] = v.w;
        } else {
            const int kk = tid >> 4;          // 0..15
            const int nn = (tid & 15) << 2;   // 0..60
            *(float4*)&Bs[kk][nn] =
                *(const float4*)(W + (size_t)(k0 + kk) * ldw + n0 + nn);
        }
        __syncthreads();

#pragma unroll
        for (int kk = 0; kk < 16; ++kk) {
            const float4 a = *(const float4*)&As[kk][ty << 2];
            const float4 b = *(const float4*)&Bs[kk][tx << 2];
            acc[0][0] += a.x * b.x; acc[0][1] += a.x * b.y; acc[0][2] += a.x * b.z; acc[0][3] += a.x * b.w;
            acc[1][0] += a.y * b.x; acc[1][1] += a.y * b.y; acc[1][2] += a.y * b.z; acc[1][3] += a.y * b.w;
            acc[2][0] += a.z * b.x; acc[2][1] += a.z * b.y; acc[2][2] += a.z * b.z; acc[2][3] += a.z * b.w;
            acc[3][0] += a.w * b.x; acc[3][1] += a.w * b.y; acc[3][2] += a.w * b.z; acc[3][3] += a.w * b.w;
        }
        __syncthreads();
    }

    // --- epilogue ---
    const int gn0 = n0 + (tx << 2);
    float4 b1 = make_float4(0.f, 0.f, 0.f, 0.f);
    float4 b2 = make_float4(0.f, 0.f, 0.f, 0.f);
    if (bias1) b1 = *(const float4*)(bias1 + gn0);
    if (bias2) b2 = *(const float4*)(bias2 + gn0);
#pragma unroll
    for (int i = 0; i < 4; ++i) {
        const int gm = m0 + (ty << 2) + i;
        if (gm >= M) continue;
        float4 r;
        r.x = acc[i][0] + b1.x + b2.x;
        r.y = acc[i][1] + b1.y + b2.y;
        r.z = acc[i][2] + b1.z + b2.z;
        r.w = acc[i][3] + b1.w + b2.w;
        if (addsrc) {
            const float4 ad = *(const float4*)(addsrc + (size_t)gm * N + gn0);
            r.x += ad.x; r.y += ad.y; r.z += ad.z; r.w += ad.w;
        }
        if (EPI == 1) {
            r.x = invleakyf(r.x); r.y = invleakyf(r.y);
            r.z = invleakyf(r.z); r.w = invleakyf(r.w);
        }
        *(float4*)(out + (size_t)gm * N + gn0) = r;
    }
}

// ---------------------------------------------------------------------------
// Encoder at t=0 only:  z0[b] = leaky(We2 @ leaky(We1 @ x0 + be1) + be2)
// One CTA per batch row.
// ---------------------------------------------------------------------------
__global__ __launch_bounds__(256)
void enc_k(const float* __restrict__ in,
           const float* __restrict__ We1, const float* __restrict__ be1,
           const float* __restrict__ We2, const float* __restrict__ be2)
{
    const int b = blockIdx.x;
    const int tid = threadIdx.x;
    __shared__ __align__(16) float xb[D_];
    __shared__ __align__(16) float hb[D_];

    xb[tid] = in[(size_t)b * T_ * INDIM_ + tid];   // row (b, t=0), cols [0,256)
    __syncthreads();

    float acc = be1[tid];
    {
        const float4* wr = (const float4*)(We1 + (size_t)tid * D_);
        const float4* xr = (const float4*)xb;
#pragma unroll 8
        for (int i = 0; i < 64; ++i) {
            const float4 w = wr[i], x = xr[i];
            acc += w.x * x.x + w.y * x.y + w.z * x.z + w.w * x.w;
        }
    }
    hb[tid] = leakyf(acc);
    __syncthreads();

    float acc2 = be2[tid];
    {
        const float4* wr = (const float4*)(We2 + (size_t)tid * D_);
        const float4* xr = (const float4*)hb;
#pragma unroll 8
        for (int i = 0; i < 64; ++i) {
            const float4 w = wr[i], x = xr[i];
            acc2 += w.x * x.x + w.y * x.y + w.z * x.z + w.w * x.w;
        }
    }
    g_z0[b * D_ + tid] = leakyf(acc2);
}

// ---------------------------------------------------------------------------
// Chunk-local scan.  One CTA per (chunk k, 16-row batch slice).
//   MODE 0: local scan (chunk 0 seeded with z0, others zero); writes only the
//           chunk-final state to flast[k*32 + b].
//   MODE 1: scan seeded with the true carry (G[k-1], or z0 for chunk 0);
//           writes inv_leaky(state) to g_w for every t.
// Thread layout: 256 threads = 64 e-groups (4 outputs) x 4 row-groups (4 rows).
// State lives in smem (16x256 f32); A streams from L2 (fits entirely, 256 KB).
// ---------------------------------------------------------------------------
template<int MODE>
__global__ __launch_bounds__(256)
void scan_k(const float* __restrict__ A,
            const float* __restrict__ carry,    // G buffer (MODE 1, k>0)
            float* __restrict__ flast)          // output (MODE 0)
{
    const int k   = blockIdx.x;
    const int b0  = blockIdx.y << 4;   // 0 or 16
    const int tid = threadIdx.x;
    const int eg  = tid & 63;
    const int rg  = tid >> 6;
    const int e0  = eg << 2;
    const int r0  = rg << 2;
    __shared__ __align__(16) float xs[16][D_];

#pragma unroll 1
    for (int r = 0; r < 16; ++r) {
        float v;
        if (k == 0)            v = g_z0[(b0 + r) * D_ + tid];
        else if (MODE == 1)    v = carry[((size_t)(k - 1) * BSZ_ + b0 + r) * D_ + tid];
        else                   v = 0.f;
        xs[r][tid] = v;
    }
    __syncthreads();

    const float4* A4 = (const float4*)A;

#pragma unroll 1
    for (int j = 0; j < LCH_; ++j) {
        const int t = k * LCH_ + j;

        float acc[4][4];
#pragma unroll
        for (int rj = 0; rj < 4; ++rj) {
            const size_t row = (size_t)(b0 + r0 + rj) * T_ + t;
            const float4 cv = *(const float4*)(g_c + row * D_ + e0);
            acc[0][rj] = cv.x; acc[1][rj] = cv.y; acc[2][rj] = cv.z; acc[3][rj] = cv.w;
        }

#pragma unroll 4
        for (int dg = 0; dg < 64; ++dg) {
            const float4 a0 = A4[(e0 + 0) * 64 + dg];
            const float4 a1 = A4[(e0 + 1) * 64 + dg];
            const float4 a2 = A4[(e0 + 2) * 64 + dg];
            const float4 a3 = A4[(e0 + 3) * 64 + dg];
#pragma unroll
            for (int rj = 0; rj < 4; ++rj) {
                const float4 xv = *(const float4*)&xs[r0 + rj][dg << 2];
                acc[0][rj] += a0.x * xv.x + a0.y * xv.y + a0.z * xv.z + a0.w * xv.w;
                acc[1][rj] += a1.x * xv.x + a1.y * xv.y + a1.z * xv.z + a1.w * xv.w;
                acc[2][rj] += a2.x * xv.x + a2.y * xv.y + a2.z * xv.z + a2.w * xv.w;
                acc[3][rj] += a3.x * xv.x + a3.y * xv.y + a3.z * xv.z + a3.w * xv.w;
            }
        }
        __syncthreads();   // all reads of old state done

#pragma unroll
        for (int rj = 0; rj < 4; ++rj) {
            const float4 nv = make_float4(acc[0][rj], acc[1][rj], acc[2][rj], acc[3][rj]);
            *(float4*)&xs[r0 + rj][e0] = nv;
            if (MODE == 1) {
                const size_t row = (size_t)(b0 + r0 + rj) * T_ + t;
                float4 wv;
                wv.x = invleakyf(nv.x); wv.y = invleakyf(nv.y);
                wv.z = invleakyf(nv.z); wv.w = invleakyf(nv.w);
                *(float4*)(g_w + row * D_ + e0) = wv;
            }
        }
        __syncthreads();
    }

    if (MODE == 0) {
#pragma unroll 1
        for (int r = 0; r < 16; ++r)
            flast[((size_t)k * BSZ_ + b0 + r) * D_ + tid] = xs[r][tid];
    }
}

// ---------------------------------------------------------------------------
// Tiny copy (Hillis-Steele passthrough rows)
// ---------------------------------------------------------------------------
__global__ void copy_k(const float* __restrict__ src, float* __restrict__ dst, int n)
{
    const int i = blockIdx.x * blockDim.x + threadIdx.x;
    if (i < n) dst[i] = src[i];
}

// ---------------------------------------------------------------------------
// Launch: encoder(t=0) -> c-GEMM -> A-power squarings -> local scans ->
//         log-depth carry combine -> carried scans (+inv_leaky) -> 2 decoder GEMMs
// ---------------------------------------------------------------------------
extern "C" void kernel_launch(void* const* d_in, const int* in_sizes, int n_in,
                              void* d_out, int out_size)
{
    (void)in_sizes; (void)n_in; (void)out_size;
    const float* P   = (const float*)d_in[0];
    const float* We1 = (const float*)d_in[1];
    const float* be1 = (const float*)d_in[2];
    const float* We2 = (const float*)d_in[3];
    const float* be2 = (const float*)d_in[4];
    const float* A_W = (const float*)d_in[5];
    const float* A_b = (const float*)d_in[6];
    const float* B_W = (const float*)d_in[7];
    const float* B_b = (const float*)d_in[8];
    const float* Wd1 = (const float*)d_in[9];
    const float* bd1 = (const float*)d_in[10];
    const float* Wd2 = (const float*)d_in[11];
    const float* bd2 = (const float*)d_in[12];
    float* out = (float*)d_out;

    float *c_p, *w_p, *g0_p, *g1_p, *pows_p;
    cudaGetSymbolAddress((void**)&c_p,    g_c);
    cudaGetSymbolAddress((void**)&w_p,    g_w);
    cudaGetSymbolAddress((void**)&g0_p,   g_gbuf0);
    cudaGetSymbolAddress((void**)&g1_p,   g_gbuf1);
    cudaGetSymbolAddress((void**)&pows_p, g_pows);

    // 1) z0 (encoder needed only at t=0 — z[:,t>0,:] is dead in the reference)
    enc_k<<<BSZ_, 256>>>(P, We1, be1, We2, be2);

    // 2) c[b,t,:] = u @ B_W^T + (B_b + A_b)
    gemm_k<true, 0><<<dim3(D_ / 64, MROWS_ / 64), 256>>>(
        P + D_, INDIM_, B_W, ALEN_, B_b, A_b, nullptr, c_p, MROWS_, D_, ALEN_);

    // 3) A^(2^i) by repeated squaring (need A^32..A^1024 for the carry combine)
    {
        const float* prev = A_W;
        for (int i = 1; i <= 10; ++i) {
            float* dst = pows_p + (size_t)i * D_ * D_;
            gemm_k<false, 0><<<dim3(4, 4), 256>>>(
                prev, D_, prev, D_, nullptr, nullptr, nullptr, dst, D_, D_, D_);
            prev = dst;
        }
    }

    // 4) Phase 1: local scans, keep chunk-final states (chunk 0 seeded with z0)
    scan_k<0><<<dim3(CCH_, 2), 256>>>(A_W, nullptr, g0_p);

    // 5) Hillis-Steele combine across chunks:  G[k] += A^(32*2^d) * G[k-2^d]
    float* bufs[2] = { g0_p, g1_p };
    for (int d = 0; d < 6; ++d) {
        float* src = bufs[d & 1];
        float* dst = bufs[(d + 1) & 1];
        const int shiftRows = 32 << d;            // 2^d chunks * 32 batch rows
        const int cnt = shiftRows * D_;
        copy_k<<<(cnt + 255) / 256, 256>>>(src, dst, cnt);
        const int Mg = CCH_ * BSZ_ - shiftRows;
        gemm_k<true, 0><<<dim3(D_ / 64, (Mg + 63) / 64), 256>>>(
            src, D_, pows_p + (size_t)(5 + d) * D_ * D_, D_,
            nullptr, nullptr, src + (size_t)shiftRows * D_,
            dst + (size_t)shiftRows * D_, Mg, D_, D_);
    }
    // after 6 levels result is back in bufs[0] = g_gbuf0

    // 6) Phase 3: re-run local scans with true carries, write inv_leaky(z1)
    scan_k<1><<<dim3(CCH_, 2), 256>>>(A_W, bufs[0], nullptr);

    // 7) Decoder: y1 = w @ Wd1^T + bd1 -> store inv_leaky(y1) into g_c
    gemm_k<true, 1><<<dim3(D_ / 64, MROWS_ / 64), 256>>>(
        w_p, D_, Wd1, D_, bd1, nullptr, nullptr, c_p, MROWS_, D_, D_);

    // 8) y = inv_leaky(y1) @ Wd2^T + bd2 -> final output
    gemm_k<true, 0><<<dim3(D_ / 64, MROWS_ / 64), 256>>>(
        c_p, D_, Wd2, D_, bd2, nullptr, nullptr, out, MROWS_, D_, D_);
}

// round 10
// speedup vs baseline: 1.0696x; 1.0696x over previous
#include <cuda_runtime.h>
#include <cstddef>

// ---------------------------------------------------------------------------
// Problem constants
// ---------------------------------------------------------------------------
#define D_      256      // STATE_DIM
#define ALEN_   128      // ACT_LEN
#define BSZ_    32       // batch
#define T_      2048     // sequence length
#define INDIM_  512      // padded input row
#define MROWS_  (BSZ_*T_)   // 65536 flattened (b,t) rows
#define CCH_    64       // scan chunks
#define LCH_    32       // chunk length  (CCH_*LCH_ == T_)

// ---------------------------------------------------------------------------
// Scratch (static device globals; no allocation allowed)
// ---------------------------------------------------------------------------
__device__ float g_c[(size_t)MROWS_ * D_];        // c[t] = Bu[t] + A_b + B_b
__device__ float g_w[(size_t)MROWS_ * D_];        // inv_leaky(z1)
__device__ float g_z0[BSZ_ * D_];                 // encoder output at t=0
__device__ float g_gbuf0[CCH_ * BSZ_ * D_];       // chunk-carry ping
__device__ float g_gbuf1[CCH_ * BSZ_ * D_];       // chunk-carry pong
__device__ float g_pows[11][D_ * D_];             // A^(2^i), i=1..10

__device__ __forceinline__ float leakyf(float x)    { return x < 0.f ? 0.01f * x : x; }
__device__ __forceinline__ float invleakyf(float x) { return x < 0.f ? x / 0.01f : x; }

// ---------------------------------------------------------------------------
// fp32 GEMM, double-buffered:  out[m][n] = epi( sum_k X[m][k]*W[n][k] + b1+b2 + add )
// W is [N,K] row-major (the "weights stored [out,in]" convention).
// Tile 64x64, BK=16, 256 threads, 4x4 register blocking, 2-stage smem pipeline
// with register prefetch (one __syncthreads per k-tile, gmem latency hidden
// under the 16-kk FFMA block).  N%64==0, K%16==0 assumed; M guarded.
// ---------------------------------------------------------------------------
template<int EPI>   // 0 = none, 1 = inv_leaky
__global__ __launch_bounds__(256)
void gemm_k(const float* __restrict__ X, int ldx,
            const float* __restrict__ W, int ldw,
            const float* __restrict__ bias1,
            const float* __restrict__ bias2,
            const float* __restrict__ addsrc,   // optional, row stride N
            float* __restrict__ out,            // row stride N
            int M, int N, int K)
{
    __shared__ __align__(16) float As[2][16][64];
    __shared__ __align__(16) float Bs[2][16][64];
    const int tid = threadIdx.x;
    const int tx = tid & 15, ty = tid >> 4;
    const int m0 = blockIdx.y << 6, n0 = blockIdx.x << 6;
    const int lar = tid >> 2;          // 0..63
    const int lak = (tid & 3) << 2;    // 0,4,8,12
    const int gm  = m0 + lar;
    const bool mv = gm < M;

    const float* xsrc = X + (size_t)(mv ? gm : 0) * ldx + lak;
    const float* wsrc = W + (size_t)(n0 + lar) * ldw + lak;

    float acc[4][4];
#pragma unroll
    for (int i = 0; i < 4; ++i)
#pragma unroll
        for (int j = 0; j < 4; ++j) acc[i][j] = 0.f;

    // prefetch + stage tile 0
    float4 av = mv ? *(const float4*)xsrc : make_float4(0.f, 0.f, 0.f, 0.f);
    float4 bv = *(const float4*)wsrc;
    As[0][lak + 0][lar] = av.x; As[0][lak + 1][lar] = av.y;
    As[0][lak + 2][lar] = av.z; As[0][lak + 3][lar] = av.w;
    Bs[0][lak + 0][lar] = bv.x; Bs[0][lak + 1][lar] = bv.y;
    Bs[0][lak + 2][lar] = bv.z; Bs[0][lak + 3][lar] = bv.w;
    __syncthreads();

    int buf = 0;
    for (int k0 = 16; ; k0 += 16) {
        const bool more = (k0 < K);
        float4 na, nb;
        if (more) {
            na = mv ? *(const float4*)(xsrc + k0) : make_float4(0.f, 0.f, 0.f, 0.f);
            nb = *(const float4*)(wsrc + k0);
        }
#pragma unroll
        for (int kk = 0; kk < 16; ++kk) {
            const float4 a = *(const float4*)&As[buf][kk][ty << 2];
            const float4 b = *(const float4*)&Bs[buf][kk][tx << 2];
            acc[0][0] += a.x * b.x; acc[0][1] += a.x * b.y; acc[0][2] += a.x * b.z; acc[0][3] += a.x * b.w;
            acc[1][0] += a.y * b.x; acc[1][1] += a.y * b.y; acc[1][2] += a.y * b.z; acc[1][3] += a.y * b.w;
            acc[2][0] += a.z * b.x; acc[2][1] += a.z * b.y; acc[2][2] += a.z * b.z; acc[2][3] += a.z * b.w;
            acc[3][0] += a.w * b.x; acc[3][1] += a.w * b.y; acc[3][2] += a.w * b.z; acc[3][3] += a.w * b.w;
        }
        if (!more) break;
        const int nbuf = buf ^ 1;
        As[nbuf][lak + 0][lar] = na.x; As[nbuf][lak + 1][lar] = na.y;
        As[nbuf][lak + 2][lar] = na.z; As[nbuf][lak + 3][lar] = na.w;
        Bs[nbuf][lak + 0][lar] = nb.x; Bs[nbuf][lak + 1][lar] = nb.y;
        Bs[nbuf][lak + 2][lar] = nb.z; Bs[nbuf][lak + 3][lar] = nb.w;
        __syncthreads();
        buf = nbuf;
    }

    // --- epilogue ---
    const int gn0 = n0 + (tx << 2);
    float4 b1 = make_float4(0.f, 0.f, 0.f, 0.f);
    float4 b2 = make_float4(0.f, 0.f, 0.f, 0.f);
    if (bias1) b1 = *(const float4*)(bias1 + gn0);
    if (bias2) b2 = *(const float4*)(bias2 + gn0);
#pragma unroll
    for (int i = 0; i < 4; ++i) {
        const int gmo = m0 + (ty << 2) + i;
        if (gmo >= M) continue;
        float4 r;
        r.x = acc[i][0] + b1.x + b2.x;
        r.y = acc[i][1] + b1.y + b2.y;
        r.z = acc[i][2] + b1.z + b2.z;
        r.w = acc[i][3] + b1.w + b2.w;
        if (addsrc) {
            const float4 ad = *(const float4*)(addsrc + (size_t)gmo * N + gn0);
            r.x += ad.x; r.y += ad.y; r.z += ad.z; r.w += ad.w;
        }
        if (EPI == 1) {
            r.x = invleakyf(r.x); r.y = invleakyf(r.y);
            r.z = invleakyf(r.z); r.w = invleakyf(r.w);
        }
        *(float4*)(out + (size_t)gmo * N + gn0) = r;
    }
}

// ---------------------------------------------------------------------------
// 256x256x256 matrix square:  O[m][n] = sum_k P[m][k] * P[k][n]
// 32x32 tiles -> 64 CTAs (vs 16 before), double-buffered. Cuts the serial
// latency of each squaring in the 10-deep power chain from ~20us to ~4us.
// ---------------------------------------------------------------------------
__global__ __launch_bounds__(256)
void sq_k(const float* __restrict__ P, float* __restrict__ O)
{
    __shared__ __align__(8) float As[2][16][32];
    __shared__ __align__(8) float Bs[2][16][32];
    const int tid = threadIdx.x;
    const int tx = tid & 15, ty = tid >> 4;
    const int m0 = blockIdx.y << 5, n0 = blockIdx.x << 5;
    const int lar = tid >> 3;            // 0..31 (m)
    const int lak = (tid & 7) << 1;      // 0,2,..,14 (k)
    const int bkk = tid >> 4;            // 0..15 (k)
    const int bnn = (tid & 15) << 1;     // 0,2,..,30 (n)

    const float* ap = P + (size_t)(m0 + lar) * D_ + lak;
    const float* bp = P + (size_t)bkk * D_ + n0 + bnn;

    float acc00 = 0.f, acc01 = 0.f, acc10 = 0.f, acc11 = 0.f;

    float2 av = *(const float2*)ap;
    float2 bv = *(const float2*)bp;
    As[0][lak + 0][lar] = av.x; As[0][lak + 1][lar] = av.y;
    Bs[0][bkk][bnn + 0] = bv.x; Bs[0][bkk][bnn + 1] = bv.y;
    __syncthreads();

    int buf = 0;
    for (int k0 = 16; ; k0 += 16) {
        const bool more = (k0 < D_);
        float2 na, nb;
        if (more) {
            na = *(const float2*)(ap + k0);
            nb = *(const float2*)(bp + (size_t)k0 * D_);
        }
#pragma unroll
        for (int kk = 0; kk < 16; ++kk) {
            const float2 a = *(const float2*)&As[buf][kk][ty << 1];
            const float2 b = *(const float2*)&Bs[buf][kk][tx << 1];
            acc00 += a.x * b.x; acc01 += a.x * b.y;
            acc10 += a.y * b.x; acc11 += a.y * b.y;
        }
        if (!more) break;
        const int nbuf = buf ^ 1;
        As[nbuf][lak + 0][lar] = na.x; As[nbuf][lak + 1][lar] = na.y;
        Bs[nbuf][bkk][bnn + 0] = nb.x; Bs[nbuf][bkk][bnn + 1] = nb.y;
        __syncthreads();
        buf = nbuf;
    }

    const int om = m0 + (ty << 1);
    const int on = n0 + (tx << 1);
    *(float2*)(O + (size_t)om * D_ + on)       = make_float2(acc00, acc01);
    *(float2*)(O + (size_t)(om + 1) * D_ + on) = make_float2(acc10, acc11);
}

// ---------------------------------------------------------------------------
// Encoder at t=0 only:  z0[b] = leaky(We2 @ leaky(We1 @ x0 + be1) + be2)
// ---------------------------------------------------------------------------
__global__ __launch_bounds__(256)
void enc_k(const float* __restrict__ in,
           const float* __restrict__ We1, const float* __restrict__ be1,
           const float* __restrict__ We2, const float* __restrict__ be2)
{
    const int b = blockIdx.x;
    const int tid = threadIdx.x;
    __shared__ __align__(16) float xb[D_];
    __shared__ __align__(16) float hb[D_];

    xb[tid] = in[(size_t)b * T_ * INDIM_ + tid];
    __syncthreads();

    float acc = be1[tid];
    {
        const float4* wr = (const float4*)(We1 + (size_t)tid * D_);
        const float4* xr = (const float4*)xb;
#pragma unroll 8
        for (int i = 0; i < 64; ++i) {
            const float4 w = wr[i], x = xr[i];
            acc += w.x * x.x + w.y * x.y + w.z * x.z + w.w * x.w;
        }
    }
    hb[tid] = leakyf(acc);
    __syncthreads();

    float acc2 = be2[tid];
    {
        const float4* wr = (const float4*)(We2 + (size_t)tid * D_);
        const float4* xr = (const float4*)hb;
#pragma unroll 8
        for (int i = 0; i < 64; ++i) {
            const float4 w = wr[i], x = xr[i];
            acc2 += w.x * x.x + w.y * x.y + w.z * x.z + w.w * x.w;
        }
    }
    g_z0[b * D_ + tid] = leakyf(acc2);
}

// ---------------------------------------------------------------------------
// Chunk-local scan (unchanged from R7 — correct and ~fma-bound; profiled this
// round via launch-order placement).  One CTA per (chunk k, 16-row slice).
// ---------------------------------------------------------------------------
template<int MODE>
__global__ __launch_bounds__(256)
void scan_k(const float* __restrict__ A,
            const float* __restrict__ carry,
            float* __restrict__ flast)
{
    const int k   = blockIdx.x;
    const int b0  = blockIdx.y << 4;
    const int tid = threadIdx.x;
    const int eg  = tid & 63;
    const int rg  = tid >> 6;
    const int e0  = eg << 2;
    const int r0  = rg << 2;
    __shared__ __align__(16) float xs[16][D_];

#pragma unroll 1
    for (int r = 0; r < 16; ++r) {
        float v;
        if (k == 0)            v = g_z0[(b0 + r) * D_ + tid];
        else if (MODE == 1)    v = carry[((size_t)(k - 1) * BSZ_ + b0 + r) * D_ + tid];
        else                   v = 0.f;
        xs[r][tid] = v;
    }
    __syncthreads();

    const float4* A4 = (const float4*)A;

#pragma unroll 1
    for (int j = 0; j < LCH_; ++j) {
        const int t = k * LCH_ + j;

        float acc[4][4];
#pragma unroll
        for (int rj = 0; rj < 4; ++rj) {
            const size_t row = (size_t)(b0 + r0 + rj) * T_ + t;
            const float4 cv = *(const float4*)(g_c + row * D_ + e0);
            acc[0][rj] = cv.x; acc[1][rj] = cv.y; acc[2][rj] = cv.z; acc[3][rj] = cv.w;
        }

#pragma unroll 4
        for (int dg = 0; dg < 64; ++dg) {
            const float4 a0 = A4[(e0 + 0) * 64 + dg];
            const float4 a1 = A4[(e0 + 1) * 64 + dg];
            const float4 a2 = A4[(e0 + 2) * 64 + dg];
            const float4 a3 = A4[(e0 + 3) * 64 + dg];
#pragma unroll
            for (int rj = 0; rj < 4; ++rj) {
                const float4 xv = *(const float4*)&xs[r0 + rj][dg << 2];
                acc[0][rj] += a0.x * xv.x + a0.y * xv.y + a0.z * xv.z + a0.w * xv.w;
                acc[1][rj] += a1.x * xv.x + a1.y * xv.y + a1.z * xv.z + a1.w * xv.w;
                acc[2][rj] += a2.x * xv.x + a2.y * xv.y + a2.z * xv.z + a2.w * xv.w;
                acc[3][rj] += a3.x * xv.x + a3.y * xv.y + a3.z * xv.z + a3.w * xv.w;
            }
        }
        __syncthreads();

#pragma unroll
        for (int rj = 0; rj < 4; ++rj) {
            const float4 nv = make_float4(acc[0][rj], acc[1][rj], acc[2][rj], acc[3][rj]);
            *(float4*)&xs[r0 + rj][e0] = nv;
            if (MODE == 1) {
                const size_t row = (size_t)(b0 + r0 + rj) * T_ + t;
                float4 wv;
                wv.x = invleakyf(nv.x); wv.y = invleakyf(nv.y);
                wv.z = invleakyf(nv.z); wv.w = invleakyf(nv.w);
                *(float4*)(g_w + row * D_ + e0) = wv;
            }
        }
        __syncthreads();
    }

    if (MODE == 0) {
#pragma unroll 1
        for (int r = 0; r < 16; ++r)
            flast[((size_t)k * BSZ_ + b0 + r) * D_ + tid] = xs[r][tid];
    }
}

// ---------------------------------------------------------------------------
// Tiny copy (Hillis-Steele passthrough rows)
// ---------------------------------------------------------------------------
__global__ void copy_k(const float* __restrict__ src, float* __restrict__ dst, int n)
{
    const int i = blockIdx.x * blockDim.x + threadIdx.x;
    if (i < n) dst[i] = src[i];
}

// ---------------------------------------------------------------------------
// Launch schedule.  Order chosen so ncu's fixed "-s 5 -c 1" profiles
// scan_k<0> (launch index 5): c-GEMM quarters (0-3), enc (4), scan0 (5).
// ---------------------------------------------------------------------------
extern "C" void kernel_launch(void* const* d_in, const int* in_sizes, int n_in,
                              void* d_out, int out_size)
{
    (void)in_sizes; (void)n_in; (void)out_size;
    const float* P   = (const float*)d_in[0];
    const float* We1 = (const float*)d_in[1];
    const float* be1 = (const float*)d_in[2];
    const float* We2 = (const float*)d_in[3];
    const float* be2 = (const float*)d_in[4];
    const float* A_W = (const float*)d_in[5];
    const float* A_b = (const float*)d_in[6];
    const float* B_W = (const float*)d_in[7];
    const float* B_b = (const float*)d_in[8];
    const float* Wd1 = (const float*)d_in[9];
    const float* bd1 = (const float*)d_in[10];
    const float* Wd2 = (const float*)d_in[11];
    const float* bd2 = (const float*)d_in[12];
    float* out = (float*)d_out;

    float *c_p, *w_p, *g0_p, *g1_p, *pows_p;
    cudaGetSymbolAddress((void**)&c_p,    g_c);
    cudaGetSymbolAddress((void**)&w_p,    g_w);
    cudaGetSymbolAddress((void**)&g0_p,   g_gbuf0);
    cudaGetSymbolAddress((void**)&g1_p,   g_gbuf1);
    cudaGetSymbolAddress((void**)&pows_p, g_pows);

    // 0-3) c[b,t,:] = u @ B_W^T + (B_b + A_b), split in 4 row-quarters
    for (int q = 0; q < 4; ++q) {
        const int MQ = MROWS_ / 4;   // 16384
        gemm_k<0><<<dim3(D_ / 64, MQ / 64), 256>>>(
            P + D_ + (size_t)q * MQ * INDIM_, INDIM_, B_W, ALEN_,
            B_b, A_b, nullptr, c_p + (size_t)q * MQ * D_, MQ, D_, ALEN_);
    }

    // 4) z0 (encoder needed only at t=0)
    enc_k<<<BSZ_, 256>>>(P, We1, be1, We2, be2);

    // 5) Phase 1: local scans (chunk 0 seeded with z0), keep chunk-final states
    scan_k<0><<<dim3(CCH_, 2), 256>>>(A_W, nullptr, g0_p);

    // 6-15) A^(2^i) by repeated squaring (need A^32..A^1024)
    {
        const float* prev = A_W;
        for (int i = 1; i <= 10; ++i) {
            float* dst = pows_p + (size_t)i * D_ * D_;
            sq_k<<<dim3(8, 8), 256>>>(prev, dst);
            prev = dst;
        }
    }

    // Hillis-Steele combine across chunks:  G[k] += A^(32*2^d) * G[k-2^d]
    float* bufs[2] = { g0_p, g1_p };
    for (int d = 0; d < 6; ++d) {
        float* src = bufs[d & 1];
        float* dst = bufs[(d + 1) & 1];
        const int shiftRows = 32 << d;
        const int cnt = shiftRows * D_;
        copy_k<<<(cnt + 255) / 256, 256>>>(src, dst, cnt);
        const int Mg = CCH_ * BSZ_ - shiftRows;
        gemm_k<0><<<dim3(D_ / 64, (Mg + 63) / 64), 256>>>(
            src, D_, pows_p + (size_t)(5 + d) * D_ * D_, D_,
            nullptr, nullptr, src + (size_t)shiftRows * D_,
            dst + (size_t)shiftRows * D_, Mg, D_, D_);
    }
    // after 6 levels result is back in bufs[0] = g_gbuf0

    // Phase 3: re-run local scans with true carries, write inv_leaky(z1)
    scan_k<1><<<dim3(CCH_, 2), 256>>>(A_W, bufs[0], nullptr);

    // Decoder: y1 = w @ Wd1^T + bd1 -> store inv_leaky(y1) into g_c
    gemm_k<1><<<dim3(D_ / 64, MROWS_ / 64), 256>>>(
        w_p, D_, Wd1, D_, bd1, nullptr, nullptr, c_p, MROWS_, D_, D_);

    // y = inv_leaky(y1) @ Wd2^T + bd2 -> final output
    gemm_k<0><<<dim3(D_ / 64, MROWS_ / 64), 256>>>(
        c_p, D_, Wd2, D_, bd2, nullptr, nullptr, out, MROWS_, D_, D_);
}

// round 12
// speedup vs baseline: 1.9028x; 1.7790x over previous
#include <cuda_runtime.h>
#include <cstddef>

// ---------------------------------------------------------------------------
// Problem constants
// ---------------------------------------------------------------------------
#define D_      256      // STATE_DIM
#define ALEN_   128      // ACT_LEN
#define BSZ_    32       // batch
#define T_      2048     // sequence length
#define INDIM_  512      // padded input row
#define MROWS_  (BSZ_*T_)   // 65536 flattened (b,t) rows
#define CCH_    64       // scan chunks
#define LCH_    32       // chunk length  (CCH_*LCH_ == T_)

// ---------------------------------------------------------------------------
// Scratch (static device globals; no allocation allowed)
// ---------------------------------------------------------------------------
__device__ float g_c[(size_t)MROWS_ * D_];        // c[t] = Bu[t] + A_b + B_b
__device__ float g_w[(size_t)MROWS_ * D_];        // inv_leaky(z1)
__device__ float g_z0[BSZ_ * D_];                 // encoder output at t=0
__device__ float g_gbuf0[CCH_ * BSZ_ * D_];       // chunk-carry ping
__device__ float g_gbuf1[CCH_ * BSZ_ * D_];       // chunk-carry pong
__device__ float g_pows[11][D_ * D_];             // A^(2^i), i=1..10
__device__ float g_At[D_ * D_];                   // A transposed: At[k][e]

__device__ __forceinline__ float leakyf(float x)    { return x < 0.f ? 0.01f * x : x; }
__device__ __forceinline__ float invleakyf(float x) { return x < 0.f ? x / 0.01f : x; }

// ---------------------------------------------------------------------------
// 256x256 transpose (two launches for profiling-order reasons):
//   At[k][e] = A[e][k].  block (32,8), grid (8,4), y0 = 0 / 128.
// ---------------------------------------------------------------------------
__global__ __launch_bounds__(256)
void tr_k(const float* __restrict__ A, float* __restrict__ At, int y0)
{
    __shared__ float t[32][33];
    const int x = blockIdx.x * 32 + threadIdx.x;         // A column (= k)
    const int ybase = y0 + blockIdx.y * 32;              // A row    (= e)
#pragma unroll
    for (int i = threadIdx.y; i < 32; i += 8)
        t[i][threadIdx.x] = A[(size_t)(ybase + i) * D_ + x];
    __syncthreads();
    const int xo = ybase + threadIdx.x;                  // e (contiguous store)
    const int yb = blockIdx.x * 32;                      // k
#pragma unroll
    for (int i = threadIdx.y; i < 32; i += 8)
        At[(size_t)(yb + i) * D_ + xo] = t[threadIdx.x][i];
}

// ---------------------------------------------------------------------------
// Big-GEMM path: 128x128 tile, BK=8, 256 threads, 8x8 per-thread microtile,
// double-buffered smem with register prefetch.
//   out[m][n] = epi( sum_k X[m][k]*W[n][k] + b1 + b2 )
// Requires M%128==0, N%128==0, K%8==0 (all true at call sites: M=32768/65536,
// N=256, K=128/256).  MAC/byte(LDS) = 1.0 (vs 0.5 in the old 64x64 kernel) --
// relieves the measured 77.9% L1 bottleneck.
// B-fragment columns are split (tx*4 and 64+tx*4) to cap LDS conflicts at 2-way.
// ---------------------------------------------------------------------------
template<int EPI>   // 0 = none, 1 = inv_leaky
__global__ __launch_bounds__(256)
void gemm128(const float* __restrict__ X, int ldx,
             const float* __restrict__ W, int ldw,
             const float* __restrict__ bias1,
             const float* __restrict__ bias2,
             float* __restrict__ out, int N, int K)
{
    constexpr int SP = 132;                    // padded row stride (floats)
    __shared__ __align__(16) float As[2][8 * SP];
    __shared__ __align__(16) float Bs[2][8 * SP];
    const int tid = threadIdx.x;
    const int tx = tid & 15, ty = tid >> 4;
    const size_t m0 = (size_t)blockIdx.y << 7;
    const int n0 = blockIdx.x << 7;
    const int row = tid >> 1;                  // 0..127
    const int kh  = (tid & 1) << 2;            // 0 or 4

    const float* xp = X + (m0 + row) * ldx + kh;
    const float* wp = W + (size_t)(n0 + row) * ldw + kh;

    float acc[8][8];
#pragma unroll
    for (int i = 0; i < 8; ++i)
#pragma unroll
        for (int j = 0; j < 8; ++j) acc[i][j] = 0.f;

    // stage tile 0
    {
        const float4 a = *(const float4*)xp;
        const float4 b = *(const float4*)wp;
        As[0][(kh + 0) * SP + row] = a.x; As[0][(kh + 1) * SP + row] = a.y;
        As[0][(kh + 2) * SP + row] = a.z; As[0][(kh + 3) * SP + row] = a.w;
        Bs[0][(kh + 0) * SP + row] = b.x; Bs[0][(kh + 1) * SP + row] = b.y;
        Bs[0][(kh + 2) * SP + row] = b.z; Bs[0][(kh + 3) * SP + row] = b.w;
    }
    __syncthreads();

    int buf = 0;
    for (int k0 = 8; ; k0 += 8) {
        const bool more = (k0 < K);
        float4 na, nb;
        if (more) { na = *(const float4*)(xp + k0); nb = *(const float4*)(wp + k0); }

#pragma unroll
        for (int kk = 0; kk < 8; ++kk) {
            const float* Ab = &As[buf][kk * SP + (ty << 3)];
            const float* Bb = &Bs[buf][kk * SP];
            const float4 a0 = *(const float4*)(Ab);
            const float4 a1 = *(const float4*)(Ab + 4);
            const float4 b0 = *(const float4*)(Bb + (tx << 2));        // cols tx*4..+3
            const float4 b1 = *(const float4*)(Bb + 64 + (tx << 2));   // cols 64+tx*4..+3
            const float am[8] = { a0.x, a0.y, a0.z, a0.w, a1.x, a1.y, a1.z, a1.w };
            const float bn[8] = { b0.x, b0.y, b0.z, b0.w, b1.x, b1.y, b1.z, b1.w };
#pragma unroll
            for (int i = 0; i < 8; ++i)
#pragma unroll
                for (int j = 0; j < 8; ++j)
                    acc[i][j] += am[i] * bn[j];
        }
        if (!more) break;
        const int nbuf = buf ^ 1;
        As[nbuf][(kh + 0) * SP + row] = na.x; As[nbuf][(kh + 1) * SP + row] = na.y;
        As[nbuf][(kh + 2) * SP + row] = na.z; As[nbuf][(kh + 3) * SP + row] = na.w;
        Bs[nbuf][(kh + 0) * SP + row] = nb.x; Bs[nbuf][(kh + 1) * SP + row] = nb.y;
        Bs[nbuf][(kh + 2) * SP + row] = nb.z; Bs[nbuf][(kh + 3) * SP + row] = nb.w;
        __syncthreads();
        buf = nbuf;
    }

    // --- epilogue ---
    const int gn1 = n0 + (tx << 2);
    const int gn2 = gn1 + 64;
    float4 c1 = make_float4(0.f, 0.f, 0.f, 0.f), c2 = c1;
    if (bias1) {
        const float4 u = *(const float4*)(bias1 + gn1);
        const float4 v = *(const float4*)(bias1 + gn2);
        c1.x += u.x; c1.y += u.y; c1.z += u.z; c1.w += u.w;
        c2.x += v.x; c2.y += v.y; c2.z += v.z; c2.w += v.w;
    }
    if (bias2) {
        const float4 u = *(const float4*)(bias2 + gn1);
        const float4 v = *(const float4*)(bias2 + gn2);
        c1.x += u.x; c1.y += u.y; c1.z += u.z; c1.w += u.w;
        c2.x += v.x; c2.y += v.y; c2.z += v.z; c2.w += v.w;
    }
#pragma unroll
    for (int i = 0; i < 8; ++i) {
        const size_t gm = m0 + (ty << 3) + i;
        float4 r1, r2;
        r1.x = acc[i][0] + c1.x; r1.y = acc[i][1] + c1.y;
        r1.z = acc[i][2] + c1.z; r1.w = acc[i][3] + c1.w;
        r2.x = acc[i][4] + c2.x; r2.y = acc[i][5] + c2.y;
        r2.z = acc[i][6] + c2.z; r2.w = acc[i][7] + c2.w;
        if (EPI == 1) {
            r1.x = invleakyf(r1.x); r1.y = invleakyf(r1.y);
            r1.z = invleakyf(r1.z); r1.w = invleakyf(r1.w);
            r2.x = invleakyf(r2.x); r2.y = invleakyf(r2.y);
            r2.z = invleakyf(r2.z); r2.w = invleakyf(r2.w);
        }
        *(float4*)(out + gm * N + gn1) = r1;
        *(float4*)(out + gm * N + gn2) = r2;
    }
}

// ---------------------------------------------------------------------------
// Old 64x64 GEMM (kept for the small Hillis-Steele combine levels, which have
// ragged M and need the addsrc path).
// ---------------------------------------------------------------------------
template<int EPI>
__global__ __launch_bounds__(256)
void gemm_k(const float* __restrict__ X, int ldx,
            const float* __restrict__ W, int ldw,
            const float* __restrict__ bias1,
            const float* __restrict__ bias2,
            const float* __restrict__ addsrc,
            float* __restrict__ out,
            int M, int N, int K)
{
    __shared__ __align__(16) float As[2][16][64];
    __shared__ __align__(16) float Bs[2][16][64];
    const int tid = threadIdx.x;
    const int tx = tid & 15, ty = tid >> 4;
    const int m0 = blockIdx.y << 6, n0 = blockIdx.x << 6;
    const int lar = tid >> 2;
    const int lak = (tid & 3) << 2;
    const int gm  = m0 + lar;
    const bool mv = gm < M;

    const float* xsrc = X + (size_t)(mv ? gm : 0) * ldx + lak;
    const float* wsrc = W + (size_t)(n0 + lar) * ldw + lak;

    float acc[4][4];
#pragma unroll
    for (int i = 0; i < 4; ++i)
#pragma unroll
        for (int j = 0; j < 4; ++j) acc[i][j] = 0.f;

    float4 av = mv ? *(const float4*)xsrc : make_float4(0.f, 0.f, 0.f, 0.f);
    float4 bv = *(const float4*)wsrc;
    As[0][lak + 0][lar] = av.x; As[0][lak + 1][lar] = av.y;
    As[0][lak + 2][lar] = av.z; As[0][lak + 3][lar] = av.w;
    Bs[0][lak + 0][lar] = bv.x; Bs[0][lak + 1][lar] = bv.y;
    Bs[0][lak + 2][lar] = bv.z; Bs[0][lak + 3][lar] = bv.w;
    __syncthreads();

    int buf = 0;
    for (int k0 = 16; ; k0 += 16) {
        const bool more = (k0 < K);
        float4 na, nb;
        if (more) {
            na = mv ? *(const float4*)(xsrc + k0) : make_float4(0.f, 0.f, 0.f, 0.f);
            nb = *(const float4*)(wsrc + k0);
        }
#pragma unroll
        for (int kk = 0; kk < 16; ++kk) {
            const float4 a = *(const float4*)&As[buf][kk][ty << 2];
            const float4 b = *(const float4*)&Bs[buf][kk][tx << 2];
            acc[0][0] += a.x * b.x; acc[0][1] += a.x * b.y; acc[0][2] += a.x * b.z; acc[0][3] += a.x * b.w;
            acc[1][0] += a.y * b.x; acc[1][1] += a.y * b.y; acc[1][2] += a.y * b.z; acc[1][3] += a.y * b.w;
            acc[2][0] += a.z * b.x; acc[2][1] += a.z * b.y; acc[2][2] += a.z * b.z; acc[2][3] += a.z * b.w;
            acc[3][0] += a.w * b.x; acc[3][1] += a.w * b.y; acc[3][2] += a.w * b.z; acc[3][3] += a.w * b.w;
        }
        if (!more) break;
        const int nbuf = buf ^ 1;
        As[nbuf][lak + 0][lar] = na.x; As[nbuf][lak + 1][lar] = na.y;
        As[nbuf][lak + 2][lar] = na.z; As[nbuf][lak + 3][lar] = na.w;
        Bs[nbuf][lak + 0][lar] = nb.x; Bs[nbuf][lak + 1][lar] = nb.y;
        Bs[nbuf][lak + 2][lar] = nb.z; Bs[nbuf][lak + 3][lar] = nb.w;
        __syncthreads();
        buf = nbuf;
    }

    const int gn0 = n0 + (tx << 2);
    float4 b1 = make_float4(0.f, 0.f, 0.f, 0.f);
    float4 b2 = make_float4(0.f, 0.f, 0.f, 0.f);
    if (bias1) b1 = *(const float4*)(bias1 + gn0);
    if (bias2) b2 = *(const float4*)(bias2 + gn0);
#pragma unroll
    for (int i = 0; i < 4; ++i) {
        const int gmo = m0 + (ty << 2) + i;
        if (gmo >= M) continue;
        float4 r;
        r.x = acc[i][0] + b1.x + b2.x;
        r.y = acc[i][1] + b1.y + b2.y;
        r.z = acc[i][2] + b1.z + b2.z;
        r.w = acc[i][3] + b1.w + b2.w;
        if (addsrc) {
            const float4 ad = *(const float4*)(addsrc + (size_t)gmo * N + gn0);
            r.x += ad.x; r.y += ad.y; r.z += ad.z; r.w += ad.w;
        }
        if (EPI == 1) {
            r.x = invleakyf(r.x); r.y = invleakyf(r.y);
            r.z = invleakyf(r.z); r.w = invleakyf(r.w);
        }
        *(float4*)(out + (size_t)gmo * N + gn0) = r;
    }
}

// ---------------------------------------------------------------------------
// 256x256x256 matrix square (power chain), 32x32 tiles, double-buffered.
// ---------------------------------------------------------------------------
__global__ __launch_bounds__(256)
void sq_k(const float* __restrict__ P, float* __restrict__ O)
{
    __shared__ __align__(8) float As[2][16][32];
    __shared__ __align__(8) float Bs[2][16][32];
    const int tid = threadIdx.x;
    const int tx = tid & 15, ty = tid >> 4;
    const int m0 = blockIdx.y << 5, n0 = blockIdx.x << 5;
    const int lar = tid >> 3;
    const int lak = (tid & 7) << 1;
    const int bkk = tid >> 4;
    const int bnn = (tid & 15) << 1;

    const float* ap = P + (size_t)(m0 + lar) * D_ + lak;
    const float* bp = P + (size_t)bkk * D_ + n0 + bnn;

    float acc00 = 0.f, acc01 = 0.f, acc10 = 0.f, acc11 = 0.f;

    float2 av = *(const float2*)ap;
    float2 bv = *(const float2*)bp;
    As[0][lak + 0][lar] = av.x; As[0][lak + 1][lar] = av.y;
    Bs[0][bkk][bnn + 0] = bv.x; Bs[0][bkk][bnn + 1] = bv.y;
    __syncthreads();

    int buf = 0;
    for (int k0 = 16; ; k0 += 16) {
        const bool more = (k0 < D_);
        float2 na, nb;
        if (more) {
            na = *(const float2*)(ap + k0);
            nb = *(const float2*)(bp + (size_t)k0 * D_);
        }
#pragma unroll
        for (int kk = 0; kk < 16; ++kk) {
            const float2 a = *(const float2*)&As[buf][kk][ty << 1];
            const float2 b = *(const float2*)&Bs[buf][kk][tx << 1];
            acc00 += a.x * b.x; acc01 += a.x * b.y;
            acc10 += a.y * b.x; acc11 += a.y * b.y;
        }
        if (!more) break;
        const int nbuf = buf ^ 1;
        As[nbuf][lak + 0][lar] = na.x; As[nbuf][lak + 1][lar] = na.y;
        Bs[nbuf][bkk][bnn + 0] = nb.x; Bs[nbuf][bkk][bnn + 1] = nb.y;
        __syncthreads();
        buf = nbuf;
    }

    const int om = m0 + (ty << 1);
    const int on = n0 + (tx << 1);
    *(float2*)(O + (size_t)om * D_ + on)       = make_float2(acc00, acc01);
    *(float2*)(O + (size_t)(om + 1) * D_ + on) = make_float2(acc10, acc11);
}

// ---------------------------------------------------------------------------
// Encoder at t=0 only
// ---------------------------------------------------------------------------
__global__ __launch_bounds__(256)
void enc_k(const float* __restrict__ in,
           const float* __restrict__ We1, const float* __restrict__ be1,
           const float* __restrict__ We2, const float* __restrict__ be2)
{
    const int b = blockIdx.x;
    const int tid = threadIdx.x;
    __shared__ __align__(16) float xb[D_];
    __shared__ __align__(16) float hb[D_];

    xb[tid] = in[(size_t)b * T_ * INDIM_ + tid];
    __syncthreads();

    float acc = be1[tid];
    {
        const float4* wr = (const float4*)(We1 + (size_t)tid * D_);
        const float4* xr = (const float4*)xb;
#pragma unroll 8
        for (int i = 0; i < 64; ++i) {
            const float4 w = wr[i], x = xr[i];
            acc += w.x * x.x + w.y * x.y + w.z * x.z + w.w * x.w;
        }
    }
    hb[tid] = leakyf(acc);
    __syncthreads();

    float acc2 = be2[tid];
    {
        const float4* wr = (const float4*)(We2 + (size_t)tid * D_);
        const float4* xr = (const float4*)hb;
#pragma unroll 8
        for (int i = 0; i < 64; ++i) {
            const float4 w = wr[i], x = xr[i];
            acc2 += w.x * x.x + w.y * x.y + w.z * x.z + w.w * x.w;
        }
    }
    g_z0[b * D_ + tid] = leakyf(acc2);
}

// ---------------------------------------------------------------------------
// Chunk-local scan using the TRANSPOSED A.
// Per dg (k-block of 4): four coalesced At loads (warp lanes step e: 512 B
// contiguous -> 4 L1 wavefronts/instr instead of 32) + four broadcast smem
// x loads, 64 FFMA.  Streaming g_c/g_w use evict-first (.cs) so At stays
// L1-resident across the 32 sequential steps.
// ---------------------------------------------------------------------------
template<int MODE>
__global__ __launch_bounds__(256)
void scan_k(const float* __restrict__ At,
            const float* __restrict__ carry,
            float* __restrict__ flast)
{
    const int k   = blockIdx.x;
    const int b0  = blockIdx.y << 4;
    const int tid = threadIdx.x;
    const int eg  = tid & 63;          // e-group: outputs e0..e0+3
    const int rg  = tid >> 6;          // row-group: rows r0..r0+3
    const int e0  = eg << 2;
    const int r0  = rg << 2;
    __shared__ __align__(16) float xs[16][D_];

#pragma unroll 1
    for (int r = 0; r < 16; ++r) {
        float v;
        if (k == 0)            v = g_z0[(b0 + r) * D_ + tid];
        else if (MODE == 1)    v = carry[((size_t)(k - 1) * BSZ_ + b0 + r) * D_ + tid];
        else                   v = 0.f;
        xs[r][tid] = v;
    }
    __syncthreads();

    const float4* At4 = (const float4*)At;   // At4[kr*64 + e/4] = At[kr][e..e+3]

#pragma unroll 1
    for (int j = 0; j < LCH_; ++j) {
        const int t = k * LCH_ + j;

        float acc[4][4];
#pragma unroll
        for (int rj = 0; rj < 4; ++rj) {
            const size_t row = (size_t)(b0 + r0 + rj) * T_ + t;
            const float4 cv = __ldcs((const float4*)(g_c + row * D_ + e0));
            acc[0][rj] = cv.x; acc[1][rj] = cv.y; acc[2][rj] = cv.z; acc[3][rj] = cv.w;
        }

#pragma unroll 4
        for (int dg = 0; dg < 64; ++dg) {
            // At rows k = 4dg..4dg+3, columns e0..e0+3  (coalesced: lanes step eg)
            const float4 a0 = At4[((dg << 2) + 0) * 64 + eg];
            const float4 a1 = At4[((dg << 2) + 1) * 64 + eg];
            const float4 a2 = At4[((dg << 2) + 2) * 64 + eg];
            const float4 a3 = At4[((dg << 2) + 3) * 64 + eg];
#pragma unroll
            for (int rj = 0; rj < 4; ++rj) {
                const float4 xv = *(const float4*)&xs[r0 + rj][dg << 2];
                acc[0][rj] += a0.x * xv.x + a1.x * xv.y + a2.x * xv.z + a3.x * xv.w;
                acc[1][rj] += a0.y * xv.x + a1.y * xv.y + a2.y * xv.z + a3.y * xv.w;
                acc[2][rj] += a0.z * xv.x + a1.z * xv.y + a2.z * xv.z + a3.z * xv.w;
                acc[3][rj] += a0.w * xv.x + a1.w * xv.y + a2.w * xv.z + a3.w * xv.w;
            }
        }
        __syncthreads();   // all reads of old state done

#pragma unroll
        for (int rj = 0; rj < 4; ++rj) {
            const float4 nv = make_float4(acc[0][rj], acc[1][rj], acc[2][rj], acc[3][rj]);
            *(float4*)&xs[r0 + rj][e0] = nv;
            if (MODE == 1) {
                const size_t row = (size_t)(b0 + r0 + rj) * T_ + t;
                float4 wv;
                wv.x = invleakyf(nv.x); wv.y = invleakyf(nv.y);
                wv.z = invleakyf(nv.z); wv.w = invleakyf(nv.w);
                __stcs((float4*)(g_w + row * D_ + e0), wv);
            }
        }
        __syncthreads();
    }

    if (MODE == 0) {
#pragma unroll 1
        for (int r = 0; r < 16; ++r)
            flast[((size_t)k * BSZ_ + b0 + r) * D_ + tid] = xs[r][tid];
    }
}

// ---------------------------------------------------------------------------
// Tiny copy (Hillis-Steele passthrough rows)
// ---------------------------------------------------------------------------
__global__ void copy_k(const float* __restrict__ src, float* __restrict__ dst, int n)
{
    const int i = blockIdx.x * blockDim.x + threadIdx.x;
    if (i < n) dst[i] = src[i];
}

// ---------------------------------------------------------------------------
// Launch schedule.  Index map (ncu profiles launch 5):
//   0 enc, 1-2 transpose halves, 3-4 c-GEMM halves, 5 scan_k<0>  <-- profiled
//   6-15 squarings, 16-27 combine, 28 scan_k<1>, 29-30 decoders
// ---------------------------------------------------------------------------
extern "C" void kernel_launch(void* const* d_in, const int* in_sizes, int n_in,
                              void* d_out, int out_size)
{
    (void)in_sizes; (void)n_in; (void)out_size;
    const float* P   = (const float*)d_in[0];
    const float* We1 = (const float*)d_in[1];
    const float* be1 = (const float*)d_in[2];
    const float* We2 = (const float*)d_in[3];
    const float* be2 = (const float*)d_in[4];
    const float* A_W = (const float*)d_in[5];
    const float* A_b = (const float*)d_in[6];
    const float* B_W = (const float*)d_in[7];
    const float* B_b = (const float*)d_in[8];
    const float* Wd1 = (const float*)d_in[9];
    const float* bd1 = (const float*)d_in[10];
    const float* Wd2 = (const float*)d_in[11];
    const float* bd2 = (const float*)d_in[12];
    float* out = (float*)d_out;

    float *c_p, *w_p, *g0_p, *g1_p, *pows_p, *at_p;
    cudaGetSymbolAddress((void**)&c_p,    g_c);
    cudaGetSymbolAddress((void**)&w_p,    g_w);
    cudaGetSymbolAddress((void**)&g0_p,   g_gbuf0);
    cudaGetSymbolAddress((void**)&g1_p,   g_gbuf1);
    cudaGetSymbolAddress((void**)&pows_p, g_pows);
    cudaGetSymbolAddress((void**)&at_p,   g_At);

    // 0) z0 (encoder needed only at t=0)
    enc_k<<<BSZ_, 256>>>(P, We1, be1, We2, be2);

    // 1-2) At = A^T (two half-launches)
    tr_k<<<dim3(8, 4), dim3(32, 8)>>>(A_W, at_p, 0);
    tr_k<<<dim3(8, 4), dim3(32, 8)>>>(A_W, at_p, 128);

    // 3-4) c[b,t,:] = u @ B_W^T + (B_b + A_b), two row-halves
    for (int q = 0; q < 2; ++q) {
        const int MQ = MROWS_ / 2;   // 32768
        gemm128<0><<<dim3(D_ / 128, MQ / 128), 256>>>(
            P + D_ + (size_t)q * MQ * INDIM_, INDIM_, B_W, ALEN_,
            B_b, A_b, c_p + (size_t)q * MQ * D_, D_, ALEN_);
    }

    // 5) Phase 1: local scans (chunk 0 seeded with z0), keep chunk-final states
    scan_k<0><<<dim3(CCH_, 2), 256>>>(at_p, nullptr, g0_p);

    // 6-15) A^(2^i) by repeated squaring (need A^32..A^1024)
    {
        const float* prev = A_W;
        for (int i = 1; i <= 10; ++i) {
            float* dst = pows_p + (size_t)i * D_ * D_;
            sq_k<<<dim3(8, 8), 256>>>(prev, dst);
            prev = dst;
        }
    }

    // Hillis-Steele combine across chunks:  G[k] += A^(32*2^d) * G[k-2^d]
    float* bufs[2] = { g0_p, g1_p };
    for (int d = 0; d < 6; ++d) {
        float* src = bufs[d & 1];
        float* dst = bufs[(d + 1) & 1];
        const int shiftRows = 32 << d;
        const int cnt = shiftRows * D_;
        copy_k<<<(cnt + 255) / 256, 256>>>(src, dst, cnt);
        const int Mg = CCH_ * BSZ_ - shiftRows;
        gemm_k<0><<<dim3(D_ / 64, (Mg + 63) / 64), 256>>>(
            src, D_, pows_p + (size_t)(5 + d) * D_ * D_, D_,
            nullptr, nullptr, src + (size_t)shiftRows * D_,
            dst + (size_t)shiftRows * D_, Mg, D_, D_);
    }
    // after 6 levels result is back in bufs[0] = g_gbuf0

    // Phase 3: re-run local scans with true carries, write inv_leaky(z1)
    scan_k<1><<<dim3(CCH_, 2), 256>>>(at_p, bufs[0], nullptr);

    // Decoder: y1 = w @ Wd1^T + bd1 -> store inv_leaky(y1) into g_c
    gemm128<1><<<dim3(D_ / 128, MROWS_ / 128), 256>>>(
        w_p, D_, Wd1, D_, bd1, nullptr, c_p, D_, D_);

    // y = inv_leaky(y1) @ Wd2^T + bd2 -> final output
    gemm128<0><<<dim3(D_ / 128, MROWS_ / 128), 256>>>(
        c_p, D_, Wd2, D_, bd2, nullptr, out, D_, D_);
}

// round 13
// speedup vs baseline: 2.0263x; 1.0649x over previous
#include <cuda_runtime.h>
#include <cstddef>

// ---------------------------------------------------------------------------
// Problem constants
// ---------------------------------------------------------------------------
#define D_      256      // STATE_DIM
#define ALEN_   128      // ACT_LEN
#define BSZ_    32       // batch
#define T_      2048     // sequence length
#define INDIM_  512      // padded input row
#define MROWS_  (BSZ_*T_)   // 65536 flattened (b,t) rows
#define CCH_    64       // scan chunks
#define LCH_    32       // chunk length  (CCH_*LCH_ == T_)

// ---------------------------------------------------------------------------
// Scratch (static device globals; no allocation allowed)
// ---------------------------------------------------------------------------
__device__ float g_c[(size_t)MROWS_ * D_];        // c[t] = Bu[t] + A_b + B_b
__device__ float g_w[(size_t)MROWS_ * D_];        // local states -> inv_leaky(z1)
__device__ float g_z0[BSZ_ * D_];                 // encoder output at t=0
__device__ float g_F[CCH_ * BSZ_ * D_];           // chunk-final local states
__device__ float g_Gx[CCH_ * BSZ_ * D_];          // per-chunk start carries (slot k)
__device__ float g_pows[33][D_ * D_];             // slots 1..32: A^n
__device__ float g_At[D_ * D_];                   // A^T           (scan operand)
__device__ float g_Mt[D_ * D_];                   // (A^32)^T      (carry operand)

__device__ __forceinline__ float leakyf(float x)    { return x < 0.f ? 0.01f * x : x; }
__device__ __forceinline__ float invleakyf(float x) { return x < 0.f ? x / 0.01f : x; }

// ---------------------------------------------------------------------------
// 256x256 transpose (half per launch): Out[k][e] = In[e][k]
// ---------------------------------------------------------------------------
__global__ __launch_bounds__(256)
void tr_k(const float* __restrict__ A, float* __restrict__ At, int y0)
{
    __shared__ float t[32][33];
    const int x = blockIdx.x * 32 + threadIdx.x;
    const int ybase = y0 + blockIdx.y * 32;
#pragma unroll
    for (int i = threadIdx.y; i < 32; i += 8)
        t[i][threadIdx.x] = A[(size_t)(ybase + i) * D_ + x];
    __syncthreads();
    const int xo = ybase + threadIdx.x;
    const int yb = blockIdx.x * 32;
#pragma unroll
    for (int i = threadIdx.y; i < 32; i += 8)
        At[(size_t)(yb + i) * D_ + xo] = t[threadIdx.x][i];
}

// ---------------------------------------------------------------------------
// 128x128x(BK=8) fp32 GEMM, 8x8 microtile, double-buffered, batched over z.
//   W_z = Wbase + z*wStep   (z = blockIdx.z)
//   MAPPED=0: out/addsrc row = gm (stride N)
//   MAPPED=1: out/addsrc element offset = ((gm&31)*T_ + (gm>>5)*LCH_ + z)*D_
// All call sites have M%128==0, N%128==0, K%8==0 -> no guards.
// ---------------------------------------------------------------------------
template<int EPI, int MAPPED>   // EPI: 0 none, 1 inv_leaky
__global__ __launch_bounds__(256)
void gemm128(const float* __restrict__ X, int ldx,
             const float* __restrict__ Wbase, int ldw, size_t wStep,
             const float* __restrict__ bias1,
             const float* __restrict__ bias2,
             const float* __restrict__ addsrc,
             float* __restrict__ out, int N, int K)
{
    constexpr int SP = 132;
    __shared__ __align__(16) float As[2][8 * SP];
    __shared__ __align__(16) float Bs[2][8 * SP];
    const int tid = threadIdx.x;
    const int tx = tid & 15, ty = tid >> 4;
    const size_t m0 = (size_t)blockIdx.y << 7;
    const int n0 = blockIdx.x << 7;
    const int z  = blockIdx.z;
    const int row = tid >> 1;
    const int kh  = (tid & 1) << 2;

    const float* W  = Wbase + (size_t)z * wStep;
    const float* xp = X + (m0 + row) * ldx + kh;
    const float* wp = W + (size_t)(n0 + row) * ldw + kh;

    float acc[8][8];
#pragma unroll
    for (int i = 0; i < 8; ++i)
#pragma unroll
        for (int j = 0; j < 8; ++j) acc[i][j] = 0.f;

    {
        const float4 a = *(const float4*)xp;
        const float4 b = *(const float4*)wp;
        As[0][(kh + 0) * SP + row] = a.x; As[0][(kh + 1) * SP + row] = a.y;
        As[0][(kh + 2) * SP + row] = a.z; As[0][(kh + 3) * SP + row] = a.w;
        Bs[0][(kh + 0) * SP + row] = b.x; Bs[0][(kh + 1) * SP + row] = b.y;
        Bs[0][(kh + 2) * SP + row] = b.z; Bs[0][(kh + 3) * SP + row] = b.w;
    }
    __syncthreads();

    int buf = 0;
    for (int k0 = 8; ; k0 += 8) {
        const bool more = (k0 < K);
        float4 na, nb;
        if (more) { na = *(const float4*)(xp + k0); nb = *(const float4*)(wp + k0); }

#pragma unroll
        for (int kk = 0; kk < 8; ++kk) {
            const float* Ab = &As[buf][kk * SP + (ty << 3)];
            const float* Bb = &Bs[buf][kk * SP];
            const float4 a0 = *(const float4*)(Ab);
            const float4 a1 = *(const float4*)(Ab + 4);
            const float4 b0 = *(const float4*)(Bb + (tx << 2));
            const float4 b1 = *(const float4*)(Bb + 64 + (tx << 2));
            const float am[8] = { a0.x, a0.y, a0.z, a0.w, a1.x, a1.y, a1.z, a1.w };
            const float bn[8] = { b0.x, b0.y, b0.z, b0.w, b1.x, b1.y, b1.z, b1.w };
#pragma unroll
            for (int i = 0; i < 8; ++i)
#pragma unroll
                for (int j = 0; j < 8; ++j)
                    acc[i][j] += am[i] * bn[j];
        }
        if (!more) break;
        const int nbuf = buf ^ 1;
        As[nbuf][(kh + 0) * SP + row] = na.x; As[nbuf][(kh + 1) * SP + row] = na.y;
        As[nbuf][(kh + 2) * SP + row] = na.z; As[nbuf][(kh + 3) * SP + row] = na.w;
        Bs[nbuf][(kh + 0) * SP + row] = nb.x; Bs[nbuf][(kh + 1) * SP + row] = nb.y;
        Bs[nbuf][(kh + 2) * SP + row] = nb.z; Bs[nbuf][(kh + 3) * SP + row] = nb.w;
        __syncthreads();
        buf = nbuf;
    }

    // --- epilogue ---
    const int gn1 = n0 + (tx << 2);
    const int gn2 = gn1 + 64;
    float4 c1 = make_float4(0.f, 0.f, 0.f, 0.f), c2 = c1;
    if (bias1) {
        const float4 u = *(const float4*)(bias1 + gn1);
        const float4 v = *(const float4*)(bias1 + gn2);
        c1.x += u.x; c1.y += u.y; c1.z += u.z; c1.w += u.w;
        c2.x += v.x; c2.y += v.y; c2.z += v.z; c2.w += v.w;
    }
    if (bias2) {
        const float4 u = *(const float4*)(bias2 + gn1);
        const float4 v = *(const float4*)(bias2 + gn2);
        c1.x += u.x; c1.y += u.y; c1.z += u.z; c1.w += u.w;
        c2.x += v.x; c2.y += v.y; c2.z += v.z; c2.w += v.w;
    }
#pragma unroll
    for (int i = 0; i < 8; ++i) {
        const size_t gm = m0 + (ty << 3) + i;
        size_t obase;
        if (MAPPED) {
            const size_t b = gm & 31;
            const size_t k = gm >> 5;
            obase = (b * T_ + k * LCH_ + z) * D_;
        } else {
            obase = gm * (size_t)N;
        }
        float4 r1, r2;
        r1.x = acc[i][0] + c1.x; r1.y = acc[i][1] + c1.y;
        r1.z = acc[i][2] + c1.z; r1.w = acc[i][3] + c1.w;
        r2.x = acc[i][4] + c2.x; r2.y = acc[i][5] + c2.y;
        r2.z = acc[i][6] + c2.z; r2.w = acc[i][7] + c2.w;
        if (addsrc) {
            const float4 u = *(const float4*)(addsrc + obase + gn1);
            const float4 v = *(const float4*)(addsrc + obase + gn2);
            r1.x += u.x; r1.y += u.y; r1.z += u.z; r1.w += u.w;
            r2.x += v.x; r2.y += v.y; r2.z += v.z; r2.w += v.w;
        }
        if (EPI == 1) {
            r1.x = invleakyf(r1.x); r1.y = invleakyf(r1.y);
            r1.z = invleakyf(r1.z); r1.w = invleakyf(r1.w);
            r2.x = invleakyf(r2.x); r2.y = invleakyf(r2.y);
            r2.z = invleakyf(r2.z); r2.w = invleakyf(r2.w);
        }
        *(float4*)(out + obase + gn1) = r1;
        *(float4*)(out + obase + gn2) = r2;
    }
}

// ---------------------------------------------------------------------------
// Batched 256^3 multiply over the power table:
//   O[outBase+z] = pows[leftSlot] * pows[rightBase + z*rightStep]
// (standard row-major product; builds A^1..A^32 in log-depth batched levels)
// ---------------------------------------------------------------------------
__global__ __launch_bounds__(256)
void mulb_k(float* __restrict__ pows, int outBase, int leftSlot,
            int rightBase, int rightStep)
{
    const float* P = pows + (size_t)leftSlot * (D_ * D_);
    const float* Q = pows + (size_t)(rightBase + blockIdx.z * rightStep) * (D_ * D_);
    float*       O = pows + (size_t)(outBase + blockIdx.z) * (D_ * D_);

    __shared__ __align__(8) float As[2][16][32];
    __shared__ __align__(8) float Bs[2][16][32];
    const int tid = threadIdx.x;
    const int tx = tid & 15, ty = tid >> 4;
    const int m0 = blockIdx.y << 5, n0 = blockIdx.x << 5;
    const int lar = tid >> 3;
    const int lak = (tid & 7) << 1;
    const int bkk = tid >> 4;
    const int bnn = (tid & 15) << 1;

    const float* ap = P + (size_t)(m0 + lar) * D_ + lak;
    const float* bp = Q + (size_t)bkk * D_ + n0 + bnn;

    float acc00 = 0.f, acc01 = 0.f, acc10 = 0.f, acc11 = 0.f;

    float2 av = *(const float2*)ap;
    float2 bv = *(const float2*)bp;
    As[0][lak + 0][lar] = av.x; As[0][lak + 1][lar] = av.y;
    Bs[0][bkk][bnn + 0] = bv.x; Bs[0][bkk][bnn + 1] = bv.y;
    __syncthreads();

    int buf = 0;
    for (int k0 = 16; ; k0 += 16) {
        const bool more = (k0 < D_);
        float2 na, nb;
        if (more) {
            na = *(const float2*)(ap + k0);
            nb = *(const float2*)(bp + (size_t)k0 * D_);
        }
#pragma unroll
        for (int kk = 0; kk < 16; ++kk) {
            const float2 a = *(const float2*)&As[buf][kk][ty << 1];
            const float2 b = *(const float2*)&Bs[buf][kk][tx << 1];
            acc00 += a.x * b.x; acc01 += a.x * b.y;
            acc10 += a.y * b.x; acc11 += a.y * b.y;
        }
        if (!more) break;
        const int nbuf = buf ^ 1;
        As[nbuf][lak + 0][lar] = na.x; As[nbuf][lak + 1][lar] = na.y;
        Bs[nbuf][bkk][bnn + 0] = nb.x; Bs[nbuf][bkk][bnn + 1] = nb.y;
        __syncthreads();
        buf = nbuf;
    }

    const int om = m0 + (ty << 1);
    const int on = n0 + (tx << 1);
    *(float2*)(O + (size_t)om * D_ + on)       = make_float2(acc00, acc01);
    *(float2*)(O + (size_t)(om + 1) * D_ + on) = make_float2(acc10, acc11);
}

// ---------------------------------------------------------------------------
// Encoder at t=0 only
// ---------------------------------------------------------------------------
__global__ __launch_bounds__(256)
void enc_k(const float* __restrict__ in,
           const float* __restrict__ We1, const float* __restrict__ be1,
           const float* __restrict__ We2, const float* __restrict__ be2)
{
    const int b = blockIdx.x;
    const int tid = threadIdx.x;
    __shared__ __align__(16) float xb[D_];
    __shared__ __align__(16) float hb[D_];

    xb[tid] = in[(size_t)b * T_ * INDIM_ + tid];
    __syncthreads();

    float acc = be1[tid];
    {
        const float4* wr = (const float4*)(We1 + (size_t)tid * D_);
        const float4* xr = (const float4*)xb;
#pragma unroll 8
        for (int i = 0; i < 64; ++i) {
            const float4 w = wr[i], x = xr[i];
            acc += w.x * x.x + w.y * x.y + w.z * x.z + w.w * x.w;
        }
    }
    hb[tid] = leakyf(acc);
    __syncthreads();

    float acc2 = be2[tid];
    {
        const float4* wr = (const float4*)(We2 + (size_t)tid * D_);
        const float4* xr = (const float4*)hb;
#pragma unroll 8
        for (int i = 0; i < 64; ++i) {
            const float4 w = wr[i], x = xr[i];
            acc2 += w.x * x.x + w.y * x.y + w.z * x.z + w.w * x.w;
        }
    }
    g_z0[b * D_ + tid] = leakyf(acc2);
}

// ---------------------------------------------------------------------------
// Phase-1 chunk-local scan (zero-seeded; chunk 0 seeded with z0).
// One CTA per (chunk k, 16-row batch slice); 128 CTAs.
// Ping-pong smem state -> ONE __syncthreads per step.
// Writes RAW local state of every step to g_w, chunk-final to g_F.
// ---------------------------------------------------------------------------
__global__ __launch_bounds__(256)
void scan1_k(const float* __restrict__ At)
{
    const int k   = blockIdx.x;
    const int b0  = blockIdx.y << 4;
    const int tid = threadIdx.x;
    const int eg  = tid & 63;
    const int rg  = tid >> 6;
    const int e0  = eg << 2;
    const int r0  = rg << 2;
    __shared__ __align__(16) float xs[2][16][D_];

#pragma unroll 1
    for (int r = 0; r < 16; ++r)
        xs[0][r][tid] = (k == 0) ? g_z0[(b0 + r) * D_ + tid] : 0.f;
    __syncthreads();

    const float4* At4 = (const float4*)At;
    int cur = 0;

#pragma unroll 1
    for (int j = 0; j < LCH_; ++j) {
        const int t = k * LCH_ + j;

        float acc[4][4];
#pragma unroll
        for (int rj = 0; rj < 4; ++rj) {
            const size_t row = (size_t)(b0 + r0 + rj) * T_ + t;
            const float4 cv = __ldcs((const float4*)(g_c + row * D_ + e0));
            acc[0][rj] = cv.x; acc[1][rj] = cv.y; acc[2][rj] = cv.z; acc[3][rj] = cv.w;
        }

#pragma unroll 4
        for (int dg = 0; dg < 64; ++dg) {
            const float4 a0 = At4[((dg << 2) + 0) * 64 + eg];
            const float4 a1 = At4[((dg << 2) + 1) * 64 + eg];
            const float4 a2 = At4[((dg << 2) + 2) * 64 + eg];
            const float4 a3 = At4[((dg << 2) + 3) * 64 + eg];
#pragma unroll
            for (int rj = 0; rj < 4; ++rj) {
                const float4 xv = *(const float4*)&xs[cur][r0 + rj][dg << 2];
                acc[0][rj] += a0.x * xv.x + a1.x * xv.y + a2.x * xv.z + a3.x * xv.w;
                acc[1][rj] += a0.y * xv.x + a1.y * xv.y + a2.y * xv.z + a3.y * xv.w;
                acc[2][rj] += a0.z * xv.x + a1.z * xv.y + a2.z * xv.z + a3.z * xv.w;
                acc[3][rj] += a0.w * xv.x + a1.w * xv.y + a2.w * xv.z + a3.w * xv.w;
            }
        }

        const int nxt = cur ^ 1;
#pragma unroll
        for (int rj = 0; rj < 4; ++rj) {
            const float4 nv = make_float4(acc[0][rj], acc[1][rj], acc[2][rj], acc[3][rj]);
            *(float4*)&xs[nxt][r0 + rj][e0] = nv;
            const size_t row = (size_t)(b0 + r0 + rj) * T_ + t;
            __stcs((float4*)(g_w + row * D_ + e0), nv);   // raw local state
        }
        __syncthreads();
        cur = nxt;
    }

#pragma unroll 1
    for (int r = 0; r < 16; ++r)
        g_F[((size_t)k * BSZ_ + b0 + r) * D_ + tid] = xs[cur][r][tid];
}

// ---------------------------------------------------------------------------
// Carry scan over chunk finals (replaces Hillis-Steele combine entirely).
// One CTA per batch row b; 256 threads = output elements e.
//   E[0] = F[0] (chunk 0 was z0-seeded -> already true)
//   E[k] = A^32 * E[k-1] + F[k]
// Writes Gx[k] = E[k-1] (start carry for chunk k); Gx[0] = 0.
// Mt[kk][e] = A^32[e][kk] -> coalesced loads.
// ---------------------------------------------------------------------------
__global__ __launch_bounds__(256)
void carry_k(const float* __restrict__ Mt)
{
    const int b = blockIdx.x;
    const int e = threadIdx.x;
    __shared__ float s[D_];

    g_Gx[(size_t)b * D_ + e] = 0.f;                       // Gx slot 0 = 0
    float v = g_F[(size_t)b * D_ + e];                    // E[0] = F[0]
    s[e] = v;
    g_Gx[((size_t)1 * BSZ_ + b) * D_ + e] = v;            // Gx slot 1 = E[0]
    __syncthreads();

#pragma unroll 1
    for (int k = 1; k < CCH_; ++k) {
        float acc = g_F[((size_t)k * BSZ_ + b) * D_ + e];
#pragma unroll 8
        for (int kk = 0; kk < D_; ++kk)
            acc += Mt[(size_t)kk * D_ + e] * s[kk];
        __syncthreads();
        s[e] = acc;
        if (k < CCH_ - 1)
            g_Gx[((size_t)(k + 1) * BSZ_ + b) * D_ + e] = acc;
        __syncthreads();
    }
}

// ---------------------------------------------------------------------------
// Tiny copy (A -> power slot 1)
// ---------------------------------------------------------------------------
__global__ void copy_k(const float* __restrict__ src, float* __restrict__ dst, int n)
{
    const int i = blockIdx.x * blockDim.x + threadIdx.x;
    if (i < n) dst[i] = src[i];
}

// ---------------------------------------------------------------------------
// Launch schedule:
//  enc, trAt x2, c-GEMM x2, scan1, copyA, powers x5, trMt x2, carry,
//  correction (1 batched launch, z=32), decoder1, decoder2
// ---------------------------------------------------------------------------
extern "C" void kernel_launch(void* const* d_in, const int* in_sizes, int n_in,
                              void* d_out, int out_size)
{
    (void)in_sizes; (void)n_in; (void)out_size;
    const float* P   = (const float*)d_in[0];
    const float* We1 = (const float*)d_in[1];
    const float* be1 = (const float*)d_in[2];
    const float* We2 = (const float*)d_in[3];
    const float* be2 = (const float*)d_in[4];
    const float* A_W = (const float*)d_in[5];
    const float* A_b = (const float*)d_in[6];
    const float* B_W = (const float*)d_in[7];
    const float* B_b = (const float*)d_in[8];
    const float* Wd1 = (const float*)d_in[9];
    const float* bd1 = (const float*)d_in[10];
    const float* Wd2 = (const float*)d_in[11];
    const float* bd2 = (const float*)d_in[12];
    float* out = (float*)d_out;

    float *c_p, *w_p, *gx_p, *pows_p, *at_p, *mt_p;
    cudaGetSymbolAddress((void**)&c_p,    g_c);
    cudaGetSymbolAddress((void**)&w_p,    g_w);
    cudaGetSymbolAddress((void**)&gx_p,   g_Gx);
    cudaGetSymbolAddress((void**)&pows_p, g_pows);
    cudaGetSymbolAddress((void**)&at_p,   g_At);
    cudaGetSymbolAddress((void**)&mt_p,   g_Mt);

    // 0) z0 (encoder needed only at t=0 — z[:,t>0,:] is dead in the reference)
    enc_k<<<BSZ_, 256>>>(P, We1, be1, We2, be2);

    // 1-2) At = A^T for the scan
    tr_k<<<dim3(8, 4), dim3(32, 8)>>>(A_W, at_p, 0);
    tr_k<<<dim3(8, 4), dim3(32, 8)>>>(A_W, at_p, 128);

    // 3-4) c[b,t,:] = u @ B_W^T + (B_b + A_b), two row-halves
    for (int q = 0; q < 2; ++q) {
        const int MQ = MROWS_ / 2;
        gemm128<0, 0><<<dim3(D_ / 128, MQ / 128), 256>>>(
            P + D_ + (size_t)q * MQ * INDIM_, INDIM_, B_W, ALEN_, 0,
            B_b, A_b, nullptr, c_p + (size_t)q * MQ * D_, D_, ALEN_);
    }

    // 5) Phase 1: zero-seeded local scans; locals -> g_w, finals -> g_F
    scan1_k<<<dim3(CCH_, 2), 256>>>(at_p);

    // Powers A^1..A^32 in log-depth batched levels
    copy_k<<<(D_ * D_ + 255) / 256, 256>>>(A_W, pows_p + (size_t)1 * D_ * D_, D_ * D_);
    mulb_k<<<dim3(8, 8, 1),  256>>>(pows_p, 2,  1, 1, 0);   // A^2
    mulb_k<<<dim3(8, 8, 2),  256>>>(pows_p, 3,  2, 1, 1);   // A^3,  A^4
    mulb_k<<<dim3(8, 8, 4),  256>>>(pows_p, 5,  4, 1, 1);   // A^5..A^8
    mulb_k<<<dim3(8, 8, 8),  256>>>(pows_p, 9,  8, 1, 1);   // A^9..A^16
    mulb_k<<<dim3(8, 8, 16), 256>>>(pows_p, 17, 16, 1, 1);  // A^17..A^32

    // Mt = (A^32)^T for the carry scan
    tr_k<<<dim3(8, 4), dim3(32, 8)>>>(pows_p + (size_t)32 * D_ * D_, mt_p, 0);
    tr_k<<<dim3(8, 4), dim3(32, 8)>>>(pows_p + (size_t)32 * D_ * D_, mt_p, 128);

    // Carry scan over chunk finals: Gx[k] = true state at start of chunk k
    carry_k<<<BSZ_, 256>>>(mt_p);

    // Correction (replaces sequential phase 3):
    //   z1[b, 32k+j] = local[b, 32k+j] + A^(j+1) * Gx[k,b]
    //   g_w <- inv_leaky(z1), one batched launch over j = blockIdx.z
    gemm128<1, 1><<<dim3(D_ / 128, (CCH_ * BSZ_) / 128, LCH_), 256>>>(
        gx_p, D_, pows_p + (size_t)1 * D_ * D_, D_, (size_t)D_ * D_,
        nullptr, nullptr, w_p, w_p, D_, D_);

    // Decoder: y1 = w @ Wd1^T + bd1 -> store inv_leaky(y1) into g_c
    gemm128<1, 0><<<dim3(D_ / 128, MROWS_ / 128), 256>>>(
        w_p, D_, Wd1, D_, 0, bd1, nullptr, nullptr, c_p, D_, D_);

    // y = inv_leaky(y1) @ Wd2^T + bd2 -> final output
    gemm128<0, 0><<<dim3(D_ / 128, MROWS_ / 128), 256>>>(
        c_p, D_, Wd2, D_, 0, bd2, nullptr, nullptr, out, D_, D_);
}